// round 1
// baseline (speedup 1.0000x reference)
#include <cuda_runtime.h>
#include <math.h>

#define B_  4
#define S_  2048
#define D_  2048
#define H_  16
#define HD_ 128

// ---------------- scratch (static device allocations; no cudaMalloc) ----------
__device__ float g_qkv[(size_t)B_ * S_ * 3 * D_];   // 8192 x 6144
__device__ float g_q  [(size_t)B_ * H_ * S_ * HD_]; // (b,h,s,hd)
__device__ float g_ctx[(size_t)B_ * S_ * D_];       // (b,s,d)

// ---------------- generic SGEMM: C[M,N] = A[M,K] @ B[K,N] ---------------------
// 128x128 tile, BK=16, 256 threads, 8x8 per thread. All dims multiples of tile.
__global__ __launch_bounds__(256) void sgemm_kernel(
    const float* __restrict__ A, const float* __restrict__ Bm,
    float* __restrict__ C, int M, int N, int K)
{
    __shared__ float As[16][128];
    __shared__ float Bs[16][128];

    const int tid = threadIdx.x;
    const int tx = tid & 15;
    const int ty = tid >> 4;
    const int ar = tid >> 1;          // A tile row 0..127
    const int ac = (tid & 1) << 3;    // A tile col 0 or 8
    const int br = tid >> 4;          // B tile row 0..15
    const int bc = (tid & 15) << 3;   // B tile col 0..120

    const float* Ab = A + (size_t)blockIdx.y * 128 * K;
    const float* Bb = Bm + (size_t)blockIdx.x * 128;

    float acc[8][8];
#pragma unroll
    for (int i = 0; i < 8; i++) {
#pragma unroll
        for (int j = 0; j < 8; j++) acc[i][j] = 0.f;
    }

    for (int kt = 0; kt < K; kt += 16) {
        float4 a0 = *(const float4*)(Ab + (size_t)ar * K + kt + ac);
        float4 a1 = *(const float4*)(Ab + (size_t)ar * K + kt + ac + 4);
        float4 b0 = *(const float4*)(Bb + (size_t)(kt + br) * N + bc);
        float4 b1 = *(const float4*)(Bb + (size_t)(kt + br) * N + bc + 4);

        As[ac + 0][ar] = a0.x; As[ac + 1][ar] = a0.y;
        As[ac + 2][ar] = a0.z; As[ac + 3][ar] = a0.w;
        As[ac + 4][ar] = a1.x; As[ac + 5][ar] = a1.y;
        As[ac + 6][ar] = a1.z; As[ac + 7][ar] = a1.w;
        *(float4*)&Bs[br][bc]     = b0;
        *(float4*)&Bs[br][bc + 4] = b1;
        __syncthreads();

#pragma unroll
        for (int kk = 0; kk < 16; kk++) {
            float ra[8], rb[8];
            *(float4*)&ra[0] = *(const float4*)&As[kk][ty * 8];
            *(float4*)&ra[4] = *(const float4*)&As[kk][ty * 8 + 4];
            *(float4*)&rb[0] = *(const float4*)&Bs[kk][tx * 8];
            *(float4*)&rb[4] = *(const float4*)&Bs[kk][tx * 8 + 4];
#pragma unroll
            for (int i = 0; i < 8; i++) {
#pragma unroll
                for (int j = 0; j < 8; j++)
                    acc[i][j] = fmaf(ra[i], rb[j], acc[i][j]);
            }
        }
        __syncthreads();
    }

    float* Cb = C + (size_t)(blockIdx.y * 128 + ty * 8) * N + blockIdx.x * 128 + tx * 8;
#pragma unroll
    for (int i = 0; i < 8; i++) {
        *(float4*)(Cb + (size_t)i * N)     = make_float4(acc[i][0], acc[i][1], acc[i][2], acc[i][3]);
        *(float4*)(Cb + (size_t)i * N + 4) = make_float4(acc[i][4], acc[i][5], acc[i][6], acc[i][7]);
    }
}

// ---------------- RoPE + scatter into (b,h,s,hd); K,V go straight to d_out ----
__global__ __launch_bounds__(256) void rope_scatter_kernel(
    const float* __restrict__ qkv,
    const float* __restrict__ cosT, const float* __restrict__ sinT,
    float* __restrict__ Qo, float* __restrict__ Ko, float* __restrict__ Vo)
{
    int idx = blockIdx.x * blockDim.x + threadIdx.x;   // over B*S*D
    int hd = idx & 127;
    int h  = (idx >> 7) & 15;
    int s  = (idx >> 11) & 2047;
    int b  = idx >> 22;

    const float* base = qkv + (size_t)(b * S_ + s) * (3 * D_);
    float c  = cosT[s * HD_ + hd];
    float sn = sinT[s * HD_ + hd];
    int col  = h * HD_ + hd;
    int pcol = (hd < 64) ? (col + 64) : (col - 64);
    float sgn = (hd < 64) ? -1.f : 1.f;

    float qv = base[col];
    float kv = base[D_ + col];
    float qr = base[pcol] * sgn;
    float kr = base[D_ + pcol] * sgn;

    size_t o = ((size_t)(b * H_ + h) * S_ + s) * HD_ + hd;
    Qo[o] = qv * c + qr * sn;
    Ko[o] = kv * c + kr * sn;
    Vo[o] = base[2 * D_ + col];
}

// ---------------- causal flash attention, fp32, BM=BN=64, 256 threads --------
#define QK_STR 132          // 128 + 4 pad (keeps float4 align, breaks conflicts)
#define P_STR  68
#define FK_SMEM_FLOATS (3 * 64 * QK_STR + 64 * P_STR)

__global__ __launch_bounds__(256) void flash_kernel(
    const float* __restrict__ Q, const float* __restrict__ K,
    const float* __restrict__ V, float* __restrict__ ctx)
{
    extern __shared__ float sh[];
    float* Qs = sh;
    float* Ks = sh + 64 * QK_STR;
    float* Vs = sh + 2 * 64 * QK_STR;
    float* Ps = sh + 3 * 64 * QK_STR;

    const int tid = threadIdx.x;
    const int tx = tid & 15;
    const int ty = tid >> 4;
    const int q0 = blockIdx.x * 64;
    const int bh = blockIdx.y;
    const float scale = 0.08838834764831845f; // 1/sqrt(128)

    const float* Qg = Q + ((size_t)bh * S_ + q0) * HD_;
    const float* Kg = K + (size_t)bh * S_ * HD_;
    const float* Vg = V + (size_t)bh * S_ * HD_;

    // load Q tile, folding in softmax scale
    for (int i = tid * 4; i < 64 * 128; i += 1024) {
        int r = i >> 7, c = i & 127;
        float4 v = *(const float4*)(Qg + (size_t)r * HD_ + c);
        *(float4*)&Qs[r * QK_STR + c] =
            make_float4(v.x * scale, v.y * scale, v.z * scale, v.w * scale);
    }

    float m[4], l[4], acc[4][8];
#pragma unroll
    for (int i = 0; i < 4; i++) {
        m[i] = -1e30f; l[i] = 0.f;
#pragma unroll
        for (int j = 0; j < 8; j++) acc[i][j] = 0.f;
    }
    __syncthreads();

    for (int ks = 0; ks <= q0; ks += 64) {
        for (int i = tid * 4; i < 64 * 128; i += 1024) {
            int r = i >> 7, c = i & 127;
            *(float4*)&Ks[r * QK_STR + c] = *(const float4*)(Kg + (size_t)(ks + r) * HD_ + c);
            *(float4*)&Vs[r * QK_STR + c] = *(const float4*)(Vg + (size_t)(ks + r) * HD_ + c);
        }
        __syncthreads();

        // scores: 4x4 per thread
        float s[4][4];
#pragma unroll
        for (int i = 0; i < 4; i++)
#pragma unroll
            for (int j = 0; j < 4; j++) s[i][j] = 0.f;

        for (int d = 0; d < 128; d += 4) {
            float4 qa[4], kb[4];
#pragma unroll
            for (int i = 0; i < 4; i++) qa[i] = *(const float4*)&Qs[(ty * 4 + i) * QK_STR + d];
#pragma unroll
            for (int j = 0; j < 4; j++) kb[j] = *(const float4*)&Ks[(tx * 4 + j) * QK_STR + d];
#pragma unroll
            for (int i = 0; i < 4; i++) {
#pragma unroll
                for (int j = 0; j < 4; j++) {
                    s[i][j] = fmaf(qa[i].x, kb[j].x, s[i][j]);
                    s[i][j] = fmaf(qa[i].y, kb[j].y, s[i][j]);
                    s[i][j] = fmaf(qa[i].z, kb[j].z, s[i][j]);
                    s[i][j] = fmaf(qa[i].w, kb[j].w, s[i][j]);
                }
            }
        }

        if (ks == q0) { // diagonal tile: mask j > i (local == global offsets here)
#pragma unroll
            for (int i = 0; i < 4; i++)
#pragma unroll
                for (int j = 0; j < 4; j++)
                    if (tx * 4 + j > ty * 4 + i) s[i][j] = -1e30f;
        }

        // row max across the 16 tx threads of this row group
        float mx[4];
#pragma unroll
        for (int i = 0; i < 4; i++)
            mx[i] = fmaxf(fmaxf(s[i][0], s[i][1]), fmaxf(s[i][2], s[i][3]));
#pragma unroll
        for (int o = 1; o < 16; o <<= 1) {
#pragma unroll
            for (int i = 0; i < 4; i++)
                mx[i] = fmaxf(mx[i], __shfl_xor_sync(0xffffffffu, mx[i], o));
        }

        float alpha[4], rs[4];
#pragma unroll
        for (int i = 0; i < 4; i++) {
            float mn = fmaxf(m[i], mx[i]);
            alpha[i] = __expf(m[i] - mn);
            m[i] = mn;
            rs[i] = 0.f;
        }
#pragma unroll
        for (int i = 0; i < 4; i++) {
#pragma unroll
            for (int j = 0; j < 4; j++) {
                float p = __expf(s[i][j] - m[i]);
                Ps[(ty * 4 + i) * P_STR + tx * 4 + j] = p;
                rs[i] += p;
            }
        }
#pragma unroll
        for (int o = 1; o < 16; o <<= 1) {
#pragma unroll
            for (int i = 0; i < 4; i++)
                rs[i] += __shfl_xor_sync(0xffffffffu, rs[i], o);
        }
#pragma unroll
        for (int i = 0; i < 4; i++) {
            l[i] = l[i] * alpha[i] + rs[i];
#pragma unroll
            for (int j = 0; j < 8; j++) acc[i][j] *= alpha[i];
        }
        __syncthreads(); // Ps fully written

        // ctx += P @ V : 4 rows x 8 cols per thread
#pragma unroll 2
        for (int kk = 0; kk < 64; kk++) {
            float pa[4];
#pragma unroll
            for (int i = 0; i < 4; i++) pa[i] = Ps[(ty * 4 + i) * P_STR + kk];
            float4 v0 = *(const float4*)&Vs[kk * QK_STR + tx * 8];
            float4 v1 = *(const float4*)&Vs[kk * QK_STR + tx * 8 + 4];
#pragma unroll
            for (int i = 0; i < 4; i++) {
                acc[i][0] = fmaf(pa[i], v0.x, acc[i][0]);
                acc[i][1] = fmaf(pa[i], v0.y, acc[i][1]);
                acc[i][2] = fmaf(pa[i], v0.z, acc[i][2]);
                acc[i][3] = fmaf(pa[i], v0.w, acc[i][3]);
                acc[i][4] = fmaf(pa[i], v1.x, acc[i][4]);
                acc[i][5] = fmaf(pa[i], v1.y, acc[i][5]);
                acc[i][6] = fmaf(pa[i], v1.z, acc[i][6]);
                acc[i][7] = fmaf(pa[i], v1.w, acc[i][7]);
            }
        }
        __syncthreads(); // before K/V/P reuse next iteration
    }

    // epilogue: write ctx in (b, s, h*128+hd) layout
    const int b = bh >> 4, h = bh & 15;
#pragma unroll
    for (int i = 0; i < 4; i++) {
        float inv = 1.f / l[i];
        int row = q0 + ty * 4 + i;
        float* dst = ctx + ((size_t)(b * S_ + row)) * D_ + h * HD_ + tx * 8;
        *(float4*)dst       = make_float4(acc[i][0] * inv, acc[i][1] * inv,
                                          acc[i][2] * inv, acc[i][3] * inv);
        *(float4*)(dst + 4) = make_float4(acc[i][4] * inv, acc[i][5] * inv,
                                          acc[i][6] * inv, acc[i][7] * inv);
    }
}

// ---------------- launch ------------------------------------------------------
extern "C" void kernel_launch(void* const* d_in, const int* in_sizes, int n_in,
                              void* d_out, int out_size)
{
    const float* x    = (const float*)d_in[0];
    const float* rc   = (const float*)d_in[1];
    const float* rs   = (const float*)d_in[2];
    const float* wqkv = (const float*)d_in[3];
    const float* wout = (const float*)d_in[4];

    float* out = (float*)d_out;
    const size_t NOUT = (size_t)B_ * S_ * D_;
    float* ko = out + NOUT;
    float* vo = out + 2 * NOUT;

    float *qkv = nullptr, *qarr = nullptr, *ctx = nullptr;
    cudaGetSymbolAddress((void**)&qkv,  g_qkv);
    cudaGetSymbolAddress((void**)&qarr, g_q);
    cudaGetSymbolAddress((void**)&ctx,  g_ctx);

    const int M = B_ * S_;            // 8192

    // 1) qkv = x @ w_qkv
    dim3 g1(3 * D_ / 128, M / 128);   // (48, 64)
    sgemm_kernel<<<g1, 256>>>(x, wqkv, qkv, M, 3 * D_, D_);

    // 2) rope + scatter (K,V land in d_out)
    rope_scatter_kernel<<<(B_ * S_ * D_) / 256, 256>>>(qkv, rc, rs, qarr, ko, vo);

    // 3) causal flash attention -> ctx (b,s,d)
    cudaFuncSetAttribute(flash_kernel, cudaFuncAttributeMaxDynamicSharedMemorySize,
                         FK_SMEM_FLOATS * (int)sizeof(float));
    flash_kernel<<<dim3(S_ / 64, B_ * H_), 256, FK_SMEM_FLOATS * sizeof(float)>>>(
        qarr, ko, vo, ctx);

    // 4) out = ctx @ w_out
    dim3 g2(D_ / 128, M / 128);       // (16, 64)
    sgemm_kernel<<<g2, 256>>>(ctx, wout, out, M, D_, D_);
}

// round 7
// speedup vs baseline: 1.1593x; 1.1593x over previous
#include <cuda_runtime.h>
#include <cstdint>
#include <math.h>
#include <mma.h>

using namespace nvcuda;

#define B_  4
#define S_  2048
#define D_  2048
#define H_  16
#define HD_ 128

// ---------------- scratch (static device allocations; no cudaMalloc) ----------
__device__ float g_qkv[(size_t)B_ * S_ * 3 * D_];   // 8192 x 6144
__device__ float g_q  [(size_t)B_ * H_ * S_ * HD_]; // (b,h,s,hd)
__device__ float g_ctx[(size_t)B_ * S_ * D_];       // (b,s,d)

// ======================= WMMA tf32 GEMM ======================================
// C[M,N] = A[M,K] @ B[K,N]   (both row-major; B used directly, no transpose)
// Tile: 128(M) x 128(N) x 32(K), 256 threads = 8 warps (2 x 4),
// per-warp 64x32 as 4x2 wmma m16n16k8 tiles. Double-buffered SMEM +
// register prefetch; tf32 round-to-nearest applied at SMEM store.

#define AS_STR 36              // 32 + 4 pad (floats)
#define BS_STR 132             // 128 + 4 pad (floats)
#define GEMM_SMEM_FLOATS (2 * 128 * AS_STR + 2 * 32 * BS_STR)

__device__ __forceinline__ float to_tf32(float x) {
    float r;
    asm("cvt.rna.tf32.f32 %0, %1;" : "=f"(r) : "f"(x));
    return r;
}

__global__ __launch_bounds__(256, 1) void gemm_tf32(
    const float* __restrict__ A, const float* __restrict__ Bw,
    float* __restrict__ C, int M, int N, int K)
{
    extern __shared__ float sh[];
    float* AsBase = sh;                         // 2 x [128][AS_STR]
    float* BsBase = sh + 2 * 128 * AS_STR;      // 2 x [32][BS_STR]

    const int tid = threadIdx.x;
    const int wid = tid >> 5;
    const int wm = (wid & 1) * 64;              // warp row offset in tile
    const int wn = (wid >> 1) * 32;             // warp col offset in tile

    // load mapping
    const int a_row = tid >> 1;                 // not used directly; see idx math
    (void)a_row;

    const float* Ab = A + (size_t)blockIdx.y * 128 * K;
    const float* Bb = Bw + (size_t)blockIdx.x * 128;

    wmma::fragment<wmma::accumulator, 16, 16, 8, float> acc[4][2];
#pragma unroll
    for (int mi = 0; mi < 4; mi++)
#pragma unroll
        for (int ni = 0; ni < 2; ni++)
            wmma::fill_fragment(acc[mi][ni], 0.0f);

    const int NC = K >> 5;                      // K / 32 chunks

    // prefetch chunk 0 into registers
    float4 pa[4], pb[4];
#pragma unroll
    for (int i = 0; i < 4; i++) {
        int idx = tid + i * 256;                // A: 1024 float4 (128 x 8)
        int r = idx >> 3, c4 = idx & 7;
        pa[i] = *(const float4*)(Ab + (size_t)r * K + c4 * 4);
    }
#pragma unroll
    for (int i = 0; i < 4; i++) {
        int idx = tid + i * 256;                // B: 1024 float4 (32 x 32)
        int r = idx >> 5, c4 = idx & 31;
        pb[i] = *(const float4*)(Bb + (size_t)r * N + c4 * 4);
    }

    for (int kt = 0; kt < NC; kt++) {
        const int buf = kt & 1;
        float* As = AsBase + buf * 128 * AS_STR;
        float* Bs = BsBase + buf * 32 * BS_STR;

        // store prefetched chunk with tf32 rounding
#pragma unroll
        for (int i = 0; i < 4; i++) {
            int idx = tid + i * 256;
            int r = idx >> 3, c = (idx & 7) * 4;
            float* d = As + r * AS_STR + c;
            d[0] = to_tf32(pa[i].x); d[1] = to_tf32(pa[i].y);
            d[2] = to_tf32(pa[i].z); d[3] = to_tf32(pa[i].w);
        }
#pragma unroll
        for (int i = 0; i < 4; i++) {
            int idx = tid + i * 256;
            int r = idx >> 5, c = (idx & 31) * 4;
            float* d = Bs + r * BS_STR + c;
            d[0] = to_tf32(pb[i].x); d[1] = to_tf32(pb[i].y);
            d[2] = to_tf32(pb[i].z); d[3] = to_tf32(pb[i].w);
        }
        __syncthreads();

        // prefetch next chunk (global -> regs, overlaps with compute below)
        if (kt + 1 < NC) {
            const float* An = Ab + (kt + 1) * 32;
            const float* Bn = Bb + (size_t)(kt + 1) * 32 * N;
#pragma unroll
            for (int i = 0; i < 4; i++) {
                int idx = tid + i * 256;
                int r = idx >> 3, c4 = idx & 7;
                pa[i] = *(const float4*)(An + (size_t)r * K + c4 * 4);
            }
#pragma unroll
            for (int i = 0; i < 4; i++) {
                int idx = tid + i * 256;
                int r = idx >> 5, c4 = idx & 31;
                pb[i] = *(const float4*)(Bn + (size_t)r * N + c4 * 4);
            }
        }

        // compute: 4 k8 steps
#pragma unroll
        for (int k8 = 0; k8 < 4; k8++) {
            const int k = k8 * 8;
            wmma::fragment<wmma::matrix_a, 16, 16, 8, wmma::precision::tf32, wmma::row_major> af[4];
            wmma::fragment<wmma::matrix_b, 16, 16, 8, wmma::precision::tf32, wmma::row_major> bf[2];
#pragma unroll
            for (int mi = 0; mi < 4; mi++)
                wmma::load_matrix_sync(af[mi], As + (wm + mi * 16) * AS_STR + k, AS_STR);
#pragma unroll
            for (int ni = 0; ni < 2; ni++)
                wmma::load_matrix_sync(bf[ni], Bs + k * BS_STR + wn + ni * 16, BS_STR);
#pragma unroll
            for (int mi = 0; mi < 4; mi++)
#pragma unroll
                for (int ni = 0; ni < 2; ni++)
                    wmma::mma_sync(acc[mi][ni], af[mi], bf[ni], acc[mi][ni]);
        }
        // NOTE: no second sync needed — next iteration stores to the other
        // buffer; the per-iteration barrier separates reuse two chunks apart.
    }

    // epilogue
    float* Cb = C + (size_t)(blockIdx.y * 128) * N + blockIdx.x * 128;
#pragma unroll
    for (int mi = 0; mi < 4; mi++)
#pragma unroll
        for (int ni = 0; ni < 2; ni++)
            wmma::store_matrix_sync(Cb + (size_t)(wm + mi * 16) * N + wn + ni * 16,
                                    acc[mi][ni], N, wmma::mem_row_major);
}

// ---------------- RoPE + scatter into (b,h,s,hd); K,V go straight to d_out ----
__global__ __launch_bounds__(256) void rope_scatter_kernel(
    const float* __restrict__ qkv,
    const float* __restrict__ cosT, const float* __restrict__ sinT,
    float* __restrict__ Qo, float* __restrict__ Ko, float* __restrict__ Vo)
{
    int idx = blockIdx.x * blockDim.x + threadIdx.x;   // over B*S*D
    int hd = idx & 127;
    int h  = (idx >> 7) & 15;
    int s  = (idx >> 11) & 2047;
    int b  = idx >> 22;

    const float* base = qkv + (size_t)(b * S_ + s) * (3 * D_);
    float c  = cosT[s * HD_ + hd];
    float sn = sinT[s * HD_ + hd];
    int col  = h * HD_ + hd;
    int pcol = (hd < 64) ? (col + 64) : (col - 64);
    float sgn = (hd < 64) ? -1.f : 1.f;

    float qv = base[col];
    float kv = base[D_ + col];
    float qr = base[pcol] * sgn;
    float kr = base[D_ + pcol] * sgn;

    size_t o = ((size_t)(b * H_ + h) * S_ + s) * HD_ + hd;
    Qo[o] = qv * c + qr * sn;
    Ko[o] = kv * c + kr * sn;
    Vo[o] = base[2 * D_ + col];
}

// ---------------- causal flash attention, fp32, BM=BN=64, 256 threads --------
#define QK_STR 132
#define P_STR  68
#define FK_SMEM_FLOATS (3 * 64 * QK_STR + 64 * P_STR)

__global__ __launch_bounds__(256) void flash_kernel(
    const float* __restrict__ Q, const float* __restrict__ K,
    const float* __restrict__ V, float* __restrict__ ctx)
{
    extern __shared__ float sh[];
    float* Qs = sh;
    float* Ks = sh + 64 * QK_STR;
    float* Vs = sh + 2 * 64 * QK_STR;
    float* Ps = sh + 3 * 64 * QK_STR;

    const int tid = threadIdx.x;
    const int tx = tid & 15;
    const int ty = tid >> 4;
    const int q0 = blockIdx.x * 64;
    const int bh = blockIdx.y;
    const float scale = 0.08838834764831845f;

    const float* Qg = Q + ((size_t)bh * S_ + q0) * HD_;
    const float* Kg = K + (size_t)bh * S_ * HD_;
    const float* Vg = V + (size_t)bh * S_ * HD_;

    for (int i = tid * 4; i < 64 * 128; i += 1024) {
        int r = i >> 7, c = i & 127;
        float4 v = *(const float4*)(Qg + (size_t)r * HD_ + c);
        *(float4*)&Qs[r * QK_STR + c] =
            make_float4(v.x * scale, v.y * scale, v.z * scale, v.w * scale);
    }

    float m[4], l[4], acc[4][8];
#pragma unroll
    for (int i = 0; i < 4; i++) {
        m[i] = -1e30f; l[i] = 0.f;
#pragma unroll
        for (int j = 0; j < 8; j++) acc[i][j] = 0.f;
    }
    __syncthreads();

    for (int ks = 0; ks <= q0; ks += 64) {
        for (int i = tid * 4; i < 64 * 128; i += 1024) {
            int r = i >> 7, c = i & 127;
            *(float4*)&Ks[r * QK_STR + c] = *(const float4*)(Kg + (size_t)(ks + r) * HD_ + c);
            *(float4*)&Vs[r * QK_STR + c] = *(const float4*)(Vg + (size_t)(ks + r) * HD_ + c);
        }
        __syncthreads();

        float s[4][4];
#pragma unroll
        for (int i = 0; i < 4; i++)
#pragma unroll
            for (int j = 0; j < 4; j++) s[i][j] = 0.f;

        for (int d = 0; d < 128; d += 4) {
            float4 qa[4], kb[4];
#pragma unroll
            for (int i = 0; i < 4; i++) qa[i] = *(const float4*)&Qs[(ty * 4 + i) * QK_STR + d];
#pragma unroll
            for (int j = 0; j < 4; j++) kb[j] = *(const float4*)&Ks[(tx * 4 + j) * QK_STR + d];
#pragma unroll
            for (int i = 0; i < 4; i++) {
#pragma unroll
                for (int j = 0; j < 4; j++) {
                    s[i][j] = fmaf(qa[i].x, kb[j].x, s[i][j]);
                    s[i][j] = fmaf(qa[i].y, kb[j].y, s[i][j]);
                    s[i][j] = fmaf(qa[i].z, kb[j].z, s[i][j]);
                    s[i][j] = fmaf(qa[i].w, kb[j].w, s[i][j]);
                }
            }
        }

        if (ks == q0) {
#pragma unroll
            for (int i = 0; i < 4; i++)
#pragma unroll
                for (int j = 0; j < 4; j++)
                    if (tx * 4 + j > ty * 4 + i) s[i][j] = -1e30f;
        }

        float mx[4];
#pragma unroll
        for (int i = 0; i < 4; i++)
            mx[i] = fmaxf(fmaxf(s[i][0], s[i][1]), fmaxf(s[i][2], s[i][3]));
#pragma unroll
        for (int o = 1; o < 16; o <<= 1) {
#pragma unroll
            for (int i = 0; i < 4; i++)
                mx[i] = fmaxf(mx[i], __shfl_xor_sync(0xffffffffu, mx[i], o));
        }

        float alpha[4], rs[4];
#pragma unroll
        for (int i = 0; i < 4; i++) {
            float mn = fmaxf(m[i], mx[i]);
            alpha[i] = __expf(m[i] - mn);
            m[i] = mn;
            rs[i] = 0.f;
        }
#pragma unroll
        for (int i = 0; i < 4; i++) {
#pragma unroll
            for (int j = 0; j < 4; j++) {
                float p = __expf(s[i][j] - m[i]);
                Ps[(ty * 4 + i) * P_STR + tx * 4 + j] = p;
                rs[i] += p;
            }
        }
#pragma unroll
        for (int o = 1; o < 16; o <<= 1) {
#pragma unroll
            for (int i = 0; i < 4; i++)
                rs[i] += __shfl_xor_sync(0xffffffffu, rs[i], o);
        }
#pragma unroll
        for (int i = 0; i < 4; i++) {
            l[i] = l[i] * alpha[i] + rs[i];
#pragma unroll
            for (int j = 0; j < 8; j++) acc[i][j] *= alpha[i];
        }
        __syncthreads();

#pragma unroll 2
        for (int kk = 0; kk < 64; kk++) {
            float pa[4];
#pragma unroll
            for (int i = 0; i < 4; i++) pa[i] = Ps[(ty * 4 + i) * P_STR + kk];
            float4 v0 = *(const float4*)&Vs[kk * QK_STR + tx * 8];
            float4 v1 = *(const float4*)&Vs[kk * QK_STR + tx * 8 + 4];
#pragma unroll
            for (int i = 0; i < 4; i++) {
                acc[i][0] = fmaf(pa[i], v0.x, acc[i][0]);
                acc[i][1] = fmaf(pa[i], v0.y, acc[i][1]);
                acc[i][2] = fmaf(pa[i], v0.z, acc[i][2]);
                acc[i][3] = fmaf(pa[i], v0.w, acc[i][3]);
                acc[i][4] = fmaf(pa[i], v1.x, acc[i][4]);
                acc[i][5] = fmaf(pa[i], v1.y, acc[i][5]);
                acc[i][6] = fmaf(pa[i], v1.z, acc[i][6]);
                acc[i][7] = fmaf(pa[i], v1.w, acc[i][7]);
            }
        }
        __syncthreads();
    }

    const int b = bh >> 4, h = bh & 15;
#pragma unroll
    for (int i = 0; i < 4; i++) {
        float inv = 1.f / l[i];
        int row = q0 + ty * 4 + i;
        float* dst = ctx + ((size_t)(b * S_ + row)) * D_ + h * HD_ + tx * 8;
        *(float4*)dst       = make_float4(acc[i][0] * inv, acc[i][1] * inv,
                                          acc[i][2] * inv, acc[i][3] * inv);
        *(float4*)(dst + 4) = make_float4(acc[i][4] * inv, acc[i][5] * inv,
                                          acc[i][6] * inv, acc[i][7] * inv);
    }
}

// ---------------- launch ------------------------------------------------------
extern "C" void kernel_launch(void* const* d_in, const int* in_sizes, int n_in,
                              void* d_out, int out_size)
{
    const float* x    = (const float*)d_in[0];
    const float* rc   = (const float*)d_in[1];
    const float* rs   = (const float*)d_in[2];
    const float* wqkv = (const float*)d_in[3];
    const float* wout = (const float*)d_in[4];

    float* out = (float*)d_out;
    const size_t NOUT = (size_t)B_ * S_ * D_;
    float* ko = out + NOUT;
    float* vo = out + 2 * NOUT;

    float *qkv = nullptr, *qarr = nullptr, *ctx = nullptr;
    cudaGetSymbolAddress((void**)&qkv,  g_qkv);
    cudaGetSymbolAddress((void**)&qarr, g_q);
    cudaGetSymbolAddress((void**)&ctx,  g_ctx);

    const int M = B_ * S_;            // 8192

    cudaFuncSetAttribute(gemm_tf32, cudaFuncAttributeMaxDynamicSharedMemorySize,
                         GEMM_SMEM_FLOATS * (int)sizeof(float));
    cudaFuncSetAttribute(flash_kernel, cudaFuncAttributeMaxDynamicSharedMemorySize,
                         FK_SMEM_FLOATS * (int)sizeof(float));

    // 1) qkv = x @ w_qkv   (wmma tf32; w_qkv is [K,N] row-major = matrix_b)
    gemm_tf32<<<dim3(3 * D_ / 128, M / 128), 256, GEMM_SMEM_FLOATS * sizeof(float)>>>(
        x, wqkv, qkv, M, 3 * D_, D_);

    // 2) rope + scatter (K,V land in d_out)
    rope_scatter_kernel<<<(B_ * S_ * D_) / 256, 256>>>(qkv, rc, rs, qarr, ko, vo);

    // 3) causal flash attention -> ctx (b,s,d)
    flash_kernel<<<dim3(S_ / 64, B_ * H_), 256, FK_SMEM_FLOATS * sizeof(float)>>>(
        qarr, ko, vo, ctx);

    // 4) out = ctx @ w_out  (wmma tf32)
    gemm_tf32<<<dim3(D_ / 128, M / 128), 256, GEMM_SMEM_FLOATS * sizeof(float)>>>(
        ctx, wout, out, M, D_, D_);
}